// round 17
// baseline (speedup 1.0000x reference)
#include <cuda_runtime.h>
#include <cuda_fp16.h>
#include <cstdint>
#include <cstddef>

#define T_DIM   8
#define N_NODES 50000
#define E_EDGES 800000
#define C_DIM   64
#define M_ROWS  (T_DIM * N_NODES)   // 400000 rows of [x | tx1]
#define BCAP    64                   // bucket capacity per node (P(deg>64) ~ 0)

// ---------------- scratch (static device globals; no allocation) ----------------
// g_deg / g_cnt are zeroed by k_gemm at the END of each invocation (and are
// zero at module load), so the prep path needs no separate zeroing kernel.
__device__ float   g_deg[N_NODES];
__device__ int     g_cnt[N_NODES];
__device__ uint2   g_cv[(size_t)N_NODES * BCAP];        // packed (src, raw ew) buckets
// node-major fp16: [node][t][32 half2] — 1KB per node
__device__ __half2 g_xh  [(size_t)M_ROWS * (C_DIM/2)];  // 51.2 MB
__device__ __half2 g_tx1h[(size_t)M_ROWS * (C_DIM/2)];  // 51.2 MB

// ---------------- prep0: block-partitioned —
//   blocks [0, TBLOCKS)  : x->fp16 node-major transpose, smem-staged,
//                          ONE cp.async.bulk store per CTA (kills STG.128 issue cost)
//   blocks >= TBLOCKS    : edge work (deg atomic + bucket fill, raw ew)
// ----------------------------------------------------------------------------
#define XCHUNKS   (M_ROWS * 8)     // 3.2M 16-byte output chunks
#define CHUNKS_PB 2560             // per transpose block (10 per thread)
#define TBLOCKS   (XCHUNKS / CHUNKS_PB)   // 1250, exact
#define SLAB_B    (CHUNKS_PB * 16) // 40960 bytes

__global__ void k_prep0(const float4* __restrict__ x4,
                        const int* __restrict__ ei, const float* __restrict__ ew) {
    __shared__ __align__(16) char slab[SLAB_B];
    int tid = threadIdx.x;
    int b   = blockIdx.x;

    if (b < TBLOCKS) {
        int base = b * CHUNKS_PB;
        #pragma unroll
        for (int it = 0; it < 10; it++) {
            int jl = it * 256 + tid;       // 0..2559
            int j  = base + jl;
            int c4 = j & 7;                // 16B chunk within the 128B t-row
            int r  = j >> 3;               // node-major row = n*8 + t
            int n  = r >> 3;
            int t  = r & 7;
            size_t s = ((size_t)t * N_NODES + n) * 16 + (size_t)c4 * 2;
            float4 v0 = __ldg(&x4[s]);
            float4 v1 = __ldg(&x4[s + 1]);
            uint4 o;
            __half2 h;
            h = __floats2half2_rn(v0.x, v0.y); o.x = *(uint32_t*)&h;
            h = __floats2half2_rn(v0.z, v0.w); o.y = *(uint32_t*)&h;
            h = __floats2half2_rn(v1.x, v1.y); o.z = *(uint32_t*)&h;
            h = __floats2half2_rn(v1.z, v1.w); o.w = *(uint32_t*)&h;
            *(uint4*)(slab + (size_t)jl * 16) = o;
        }
        __syncthreads();
        if (tid == 0) {
            asm volatile("fence.proxy.async.shared::cta;" ::: "memory");
            uint32_t saddr = (uint32_t)__cvta_generic_to_shared(slab);
            const char* gdst = (const char*)g_xh + (size_t)base * 16;
            asm volatile(
                "cp.async.bulk.global.shared::cta.bulk_group [%0], [%1], %2;"
                :: "l"(gdst), "r"(saddr), "r"((uint32_t)SLAB_B) : "memory");
            asm volatile("cp.async.bulk.commit_group;" ::: "memory");
            asm volatile("cp.async.bulk.wait_group.read 0;" ::: "memory");
        }
    } else {
        int e = (b - TBLOCKS) * 256 + tid;
        if (e < E_EDGES) {
            int s = ei[e];
            int d = ei[E_EDGES + e];
            float w = ew[e];
            atomicAdd(&g_deg[s], w);            // g_deg pre-zeroed by prior k_gemm
            int p = atomicAdd(&g_cnt[d], 1);    // g_cnt pre-zeroed by prior k_gemm
            if (p < BCAP) {
                uint2 cv;
                cv.x = (uint32_t)s;
                cv.y = __float_as_uint(w);      // raw weight; normalized in gather
                g_cv[((size_t)d << 6) + p] = cv;
            }
        }
    }
}

// ---------------- gather: one warp per dst node, lane owns 32B slice;
//                  nw computed on the fly (dinv hidden under L2 latency) ----------------
__device__ __forceinline__ float dinv_of(float dg) {
    return (dg > 0.f) ? rsqrtf(fmaxf(dg, 1e-12f)) : 0.f;
}

__global__ void k_gather() {
    int warp = (blockIdx.x * blockDim.x + threadIdx.x) >> 5;
    int lane = threadIdx.x & 31;
    if (warp >= N_NODES) return;
    int cnt = 0;
    float dinvD = 0.f;
    if (lane == 0) {
        cnt = g_cnt[warp];
        dinvD = dinv_of(g_deg[warp]);
    }
    cnt   = __shfl_sync(0xffffffffu, cnt, 0);
    dinvD = __shfl_sync(0xffffffffu, dinvD, 0);
    if (cnt > BCAP) cnt = BCAP;
    const uint2* __restrict__ bucket = g_cv + ((size_t)warp << 6);

    float2 acc[8];
    #pragma unroll
    for (int q = 0; q < 8; q++) acc[q] = make_float2(0.f, 0.f);

    const char* xbase = (const char*)g_xh + (size_t)lane * 32;

    int e = 0;
    for (; e + 1 < cnt; e += 2) {
        uint2 cv0 = __ldg(&bucket[e]);
        uint2 cv1 = __ldg(&bucket[e + 1]);
        float v0 = -__uint_as_float(cv0.y) * dinv_of(__ldg(&g_deg[cv0.x])) * dinvD;
        float v1 = -__uint_as_float(cv1.y) * dinv_of(__ldg(&g_deg[cv1.x])) * dinvD;
        const uint4* p0 = (const uint4*)(xbase + (size_t)cv0.x * 1024);
        const uint4* p1 = (const uint4*)(xbase + (size_t)cv1.x * 1024);
        uint4 a0 = __ldg(p0), b0 = __ldg(p0 + 1);
        uint4 a1 = __ldg(p1), b1 = __ldg(p1 + 1);
        const uint32_t* w0 = (const uint32_t*)&a0;
        const uint32_t* u0 = (const uint32_t*)&b0;
        const uint32_t* w1 = (const uint32_t*)&a1;
        const uint32_t* u1 = (const uint32_t*)&b1;
        #pragma unroll
        for (int q = 0; q < 4; q++) {
            float2 f;
            f = __half22float2(*(const __half2*)&w0[q]);
            acc[q].x = fmaf(v0, f.x, acc[q].x); acc[q].y = fmaf(v0, f.y, acc[q].y);
            f = __half22float2(*(const __half2*)&u0[q]);
            acc[4+q].x = fmaf(v0, f.x, acc[4+q].x); acc[4+q].y = fmaf(v0, f.y, acc[4+q].y);
            f = __half22float2(*(const __half2*)&w1[q]);
            acc[q].x = fmaf(v1, f.x, acc[q].x); acc[q].y = fmaf(v1, f.y, acc[q].y);
            f = __half22float2(*(const __half2*)&u1[q]);
            acc[4+q].x = fmaf(v1, f.x, acc[4+q].x); acc[4+q].y = fmaf(v1, f.y, acc[4+q].y);
        }
    }
    if (e < cnt) {
        uint2 cv0 = __ldg(&bucket[e]);
        float v0 = -__uint_as_float(cv0.y) * dinv_of(__ldg(&g_deg[cv0.x])) * dinvD;
        const uint4* p0 = (const uint4*)(xbase + (size_t)cv0.x * 1024);
        uint4 a0 = __ldg(p0), b0 = __ldg(p0 + 1);
        const uint32_t* w0 = (const uint32_t*)&a0;
        const uint32_t* u0 = (const uint32_t*)&b0;
        #pragma unroll
        for (int q = 0; q < 4; q++) {
            float2 f;
            f = __half22float2(*(const __half2*)&w0[q]);
            acc[q].x = fmaf(v0, f.x, acc[q].x); acc[q].y = fmaf(v0, f.y, acc[q].y);
            f = __half22float2(*(const __half2*)&u0[q]);
            acc[4+q].x = fmaf(v0, f.x, acc[4+q].x); acc[4+q].y = fmaf(v0, f.y, acc[4+q].y);
        }
    }

    uint4 o0, o1;
    uint32_t* w = (uint32_t*)&o0;
    uint32_t* u = (uint32_t*)&o1;
    #pragma unroll
    for (int q = 0; q < 4; q++) {
        __half2 h0 = __floats2half2_rn(acc[q].x, acc[q].y);
        __half2 h1 = __floats2half2_rn(acc[4+q].x, acc[4+q].y);
        w[q] = *(uint32_t*)&h0;
        u[q] = *(uint32_t*)&h1;
    }
    uint4* op = (uint4*)((char*)g_tx1h + (size_t)warp * 1024 + (size_t)lane * 32);
    op[0] = o0;
    op[1] = o1;
}

// ============================================================================
// HMMA fp16 GEMM — 2 CTAs/SM: grid 296, 256 threads, 64x128 tile, warp = 32x32,
// ldmatrix frags, 2-stage cp.async, tanh.approx epilogue.
// Zeroes g_cnt/g_deg for next invocation.
// ============================================================================

#define TILE_ROWS 64
#define TILES     (M_ROWS / TILE_ROWS)   // 6250
#define GRID_GEMM 296
#define GTHREADS  256

#define ASTRIDE 272u
#define ATILE   ((uint32_t)TILE_ROWS * ASTRIDE)   // 17408
#define NBUF    2
#define OFF_W   (NBUF * ATILE)
#define WTILE   (128u * ASTRIDE)                  // 34816 (W is 128x128)
#define DSMEM_BYTES (NBUF * ATILE + WTILE)        // 69632

#define CP_ASYNC16(dst, src) \
    asm volatile("cp.async.cg.shared.global [%0], [%1], 16;" :: "r"(dst), "l"(src))
#define CP_COMMIT() asm volatile("cp.async.commit_group;" ::: "memory")
#define CP_WAIT(n)  asm volatile("cp.async.wait_group %0;" :: "n"(n) : "memory")

__device__ __forceinline__ void mma_fp16(float* c, const uint32_t* a,
                                         uint32_t b0, uint32_t b1) {
    asm volatile(
        "mma.sync.aligned.m16n8k16.row.col.f32.f16.f16.f32 "
        "{%0,%1,%2,%3}, {%4,%5,%6,%7}, {%8,%9}, {%0,%1,%2,%3};"
        : "+f"(c[0]), "+f"(c[1]), "+f"(c[2]), "+f"(c[3])
        : "r"(a[0]), "r"(a[1]), "r"(a[2]), "r"(a[3]), "r"(b0), "r"(b1));
}

__device__ __forceinline__ void ldsm_x4(uint32_t* d, uint32_t addr) {
    asm volatile("ldmatrix.sync.aligned.m8n8.x4.shared.b16 {%0,%1,%2,%3}, [%4];"
                 : "=r"(d[0]), "=r"(d[1]), "=r"(d[2]), "=r"(d[3]) : "r"(addr));
}

__device__ __forceinline__ float tanh_fast(float x) {
    float r;
    asm("tanh.approx.f32 %0, %1;" : "=f"(r) : "f"(x));
    return r;
}

__device__ __forceinline__ void prefetchA(int tile, uint32_t dstBase, int tid) {
    int rowBase = tile * TILE_ROWS;
    #pragma unroll
    for (int it = 0; it < 4; it++) {
        int chunk = tid + it * GTHREADS;   // 0..1023 chunks of 16B (64 rows x 16)
        int r   = chunk >> 4;
        int c16 = chunk & 15;
        size_t row = (size_t)(rowBase + r);
        const void* src = (c16 < 8)
            ? (const void*)(g_xh   + row * 32 + c16 * 4)
            : (const void*)(g_tx1h + row * 32 + (c16 - 8) * 4);
        uint32_t dst = dstBase + (uint32_t)r * ASTRIDE + (uint32_t)c16 * 16u;
        CP_ASYNC16(dst, src);
    }
    CP_COMMIT();
}

__global__ void __launch_bounds__(GTHREADS, 2) k_gemm(
    const float* __restrict__ Wxz0, const float* __restrict__ Wxz1,
    const float* __restrict__ Wxh0, const float* __restrict__ Wxh1,
    const float* __restrict__ bxz,  const float* __restrict__ bhz,
    const float* __restrict__ bxh,  const float* __restrict__ bhh,
    const float* __restrict__ wlin, const float* __restrict__ blin,
    float* __restrict__ out)
{
    extern __shared__ char dsm[];
    __shared__ float sBZ[64], sBH[64], sWl[64];
    __shared__ float sRed[TILE_ROWS][4];

    char* WTh = dsm + OFF_W;
    uint32_t smemBase = (uint32_t)__cvta_generic_to_shared(dsm);
    uint32_t smemW32  = smemBase + OFF_W;

    int tid  = threadIdx.x;
    int wid  = tid >> 5;
    int lane = tid & 31;
    int bid  = blockIdx.x;
    int n = (TILES - bid + GRID_GEMM - 1) / GRID_GEMM;

    // zero cnt/deg for the NEXT kernel_launch invocation
    for (int i = bid * GTHREADS + tid; i < N_NODES; i += GRID_GEMM * GTHREADS) {
        g_cnt[i] = 0;
        g_deg[i] = 0.f;
    }

    int wm = wid >> 2;           // 0..1 : rows wm*32 ..
    int wn = wid & 3;            // 0..3 : Z cols wn*16.., H cols 64+wn*16..

    for (int idx = tid; idx < 16384; idx += GTHREADS) {
        int nn = idx >> 7;
        int k  = idx & 127;
        float v;
        if (k < 64) v = (nn < 64) ? Wxz0[k * 64 + nn]        : Wxh0[k * 64 + (nn - 64)];
        else        v = (nn < 64) ? Wxz1[(k - 64) * 64 + nn] : Wxh1[(k - 64) * 64 + (nn - 64)];
        *(__half*)(WTh + (uint32_t)nn * ASTRIDE + (uint32_t)k * 2u) = __float2half_rn(v);
    }
    if (tid < 64) {
        sBZ[tid] = bxz[tid] + bhz[tid];
        sBH[tid] = bxh[tid] + bhh[tid];
        sWl[tid] = wlin[tid];
    }
    float blin0 = blin[0];

    // ldmatrix per-lane addresses
    uint32_t aOff[2];   // relative to A-buffer base
    uint32_t bAddr[2];  // absolute (W tile fixed)
    {
        int m = lane >> 3, r = lane & 7;
        #pragma unroll
        for (int mt = 0; mt < 2; mt++) {
            int rowA = wm * 32 + mt * 16 + ((m & 1) << 3) + r;
            aOff[mt] = (uint32_t)rowA * ASTRIDE + (uint32_t)((m >> 1) << 4);
        }
        int q = lane >> 3;
        #pragma unroll
        for (int g = 0; g < 2; g++) {
            int nt  = g * 2 + (q >> 1);
            int col = wn * 16 + ((nt & 1) << 3) + ((nt >> 1) << 6);
            bAddr[g] = smemW32 + (uint32_t)(col + r) * ASTRIDE + (uint32_t)((q & 1) << 4);
        }
    }

    prefetchA(bid, smemBase, tid);
    if (n > 1) prefetchA(bid + GRID_GEMM, smemBase + ATILE, tid);

    for (int t = 0; t < n; t++) {
        if (t + 1 < n) { CP_WAIT(1); }
        else           { CP_WAIT(0); }
        __syncthreads();

        uint32_t aBuf = smemBase + (uint32_t)(t & 1) * ATILE;

        float acc[2][4][4];
        #pragma unroll
        for (int mt = 0; mt < 2; mt++)
            #pragma unroll
            for (int nt = 0; nt < 4; nt++)
                #pragma unroll
                for (int q = 0; q < 4; q++) acc[mt][nt][q] = 0.f;

        #pragma unroll
        for (int ks = 0; ks < 8; ks++) {
            uint32_t kkb = (uint32_t)ks * 32u;
            uint32_t a[2][4], B[2][4];
            ldsm_x4(a[0], aBuf + aOff[0] + kkb);
            ldsm_x4(a[1], aBuf + aOff[1] + kkb);
            ldsm_x4(B[0], bAddr[0] + kkb);
            ldsm_x4(B[1], bAddr[1] + kkb);
            #pragma unroll
            for (int nt = 0; nt < 4; nt++) {
                uint32_t b0 = B[nt >> 1][(nt & 1) * 2];
                uint32_t b1 = B[nt >> 1][(nt & 1) * 2 + 1];
                mma_fp16(acc[0][nt], a[0], b0, b1);
                mma_fp16(acc[1][nt], a[1], b0, b1);
            }
        }
        __syncthreads();
        if (t + 2 < n)
            prefetchA(bid + (t + 2) * GRID_GEMM, smemBase + (uint32_t)(t & 1) * ATILE, tid);

        // register epilogue (tanh.approx): z = 0.5+0.5*ta, (1-z)*th = 0.5*(1-ta)*th
        int rA = lane >> 2;
        int cA = (lane & 3) * 2;
        float s0[2], s1[2];
        #pragma unroll
        for (int mt = 0; mt < 2; mt++) { s0[mt] = 0.f; s1[mt] = 0.f; }
        #pragma unroll
        for (int mt = 0; mt < 2; mt++) {
            #pragma unroll
            for (int ntc = 0; ntc < 2; ntc++) {
                const float* aZ = acc[mt][ntc];
                const float* aH = acc[mt][ntc + 2];
                int cbase = wn * 16 + ntc * 8 + cA;
                #pragma unroll
                for (int u = 0; u < 2; u++) {
                    int c = cbase + u;
                    float bz = sBZ[c], bh = sBH[c], w = sWl[c];
                    {
                        float ta = tanh_fast((aZ[u] + bz) * 0.5f);
                        float th = tanh_fast(aH[u] + bh);
                        float h  = fmaxf(0.5f * (1.f - ta) * th, 0.f);
                        s0[mt] = fmaf(h, w, s0[mt]);
                    }
                    {
                        float ta = tanh_fast((aZ[2 + u] + bz) * 0.5f);
                        float th = tanh_fast(aH[2 + u] + bh);
                        float h  = fmaxf(0.5f * (1.f - ta) * th, 0.f);
                        s1[mt] = fmaf(h, w, s1[mt]);
                    }
                }
            }
        }
        #pragma unroll
        for (int mt = 0; mt < 2; mt++) {
            s0[mt] += __shfl_xor_sync(0xffffffffu, s0[mt], 1);
            s0[mt] += __shfl_xor_sync(0xffffffffu, s0[mt], 2);
            s1[mt] += __shfl_xor_sync(0xffffffffu, s1[mt], 1);
            s1[mt] += __shfl_xor_sync(0xffffffffu, s1[mt], 2);
        }
        if ((lane & 3) == 0) {
            #pragma unroll
            for (int mt = 0; mt < 2; mt++) {
                int r = wm * 32 + mt * 16 + rA;
                sRed[r][wn]     = s0[mt];
                sRed[r + 8][wn] = s1[mt];
            }
        }
        __syncthreads();
        if (tid < TILE_ROWS) {
            float v = sRed[tid][0] + sRed[tid][1] + sRed[tid][2] + sRed[tid][3];
            int rg   = (bid + t * GRID_GEMM) * TILE_ROWS + tid;   // row' = node*8 + tt
            int node = rg >> 3;
            int tt   = rg & 7;
            out[tt * N_NODES + node] = v + blin0;
        }
    }
}

// ---------------- launch ----------------
extern "C" void kernel_launch(void* const* d_in, const int* in_sizes, int n_in,
                              void* d_out, int out_size)
{
    const float* x    = (const float*)d_in[0];
    const int*   ei   = (const int*)  d_in[1];
    const float* ew   = (const float*)d_in[2];
    const float* Wxz0 = (const float*)d_in[3];
    const float* Wxz1 = (const float*)d_in[4];
    const float* bxz  = (const float*)d_in[5];
    const float* bhz  = (const float*)d_in[8];
    const float* Wxh0 = (const float*)d_in[15];
    const float* Wxh1 = (const float*)d_in[16];
    const float* bxh  = (const float*)d_in[17];
    const float* bhh  = (const float*)d_in[20];
    const float* Wlin = (const float*)d_in[21];
    const float* blin = (const float*)d_in[22];
    float* out = (float*)d_out;

    cudaFuncSetAttribute(k_gemm, cudaFuncAttributeMaxDynamicSharedMemorySize, DSMEM_BYTES);

    const int NB_P = TBLOCKS + (E_EDGES + 255) / 256;   // 1250 + 3125 blocks

    k_prep0  <<<NB_P, 256>>>((const float4*)x, ei, ew);  // 1: bulk-store transpose ∥ edges
    k_gather <<<(N_NODES * 32 + 255) / 256, 256>>>();    // 2: 1 warp/node, nw on the fly
    k_gemm   <<<GRID_GEMM, GTHREADS, DSMEM_BYTES>>>(Wxz0, Wxz1, Wxh0, Wxh1,
                                                    bxz, bhz, bxh, bhh, Wlin, blin, out);
}